// round 2
// baseline (speedup 1.0000x reference)
#include <cuda_runtime.h>

// CrossNetwork: x_l = x0 * (x_l . W_l) + b_l + x_l, L=6 layers.
// Algebraic identity: x_l = alpha_l * x0 + sum_{i<l} b_i, with
//   d_l  = x0 . W_l                       (per-row, 6 dots in one pass)
//   C_l  = (sum_{i<l} b_i) . W_l          (row-independent scalars)
//   s_l  = alpha_l * d_l + C_l ; alpha_{l+1} = alpha_l + s_l ; alpha_0 = 1
//   out  = alpha_L * x0 + sum_i b_i
// => single read of x, single write of out: ~256 MB HBM traffic total.

#define D_DIM 2048
#define L_DIM 6
#define D_VEC (D_DIM / 4)      // 512 float4 per row
#define TPB   256              // 8 floats (2 float4) per thread

__device__ float g_C[L_DIM];        // C_l scalars
__device__ float g_bsum[D_DIM];     // sum_i b_i

// ---------------------------------------------------------------------------
// Kernel 1: one block. Computes g_C and g_bsum. Negligible cost (~96 KB read).
// ---------------------------------------------------------------------------
__global__ __launch_bounds__(TPB) void precompute_kernel(
    const float* __restrict__ W, const float* __restrict__ b)
{
    const int t = threadIdx.x;
    float partialC[L_DIM];
#pragma unroll
    for (int l = 0; l < L_DIM; ++l) partialC[l] = 0.f;

    // Each thread handles 8 strided columns.
    for (int k = 0; k < D_DIM / TPB; ++k) {
        const int d = t + k * TPB;
        float pre = 0.f;  // prefix sum of b_i[d] for i < l
#pragma unroll
        for (int l = 0; l < L_DIM; ++l) {
            partialC[l] += pre * W[l * D_DIM + d];
            pre += b[l * D_DIM + d];
        }
        g_bsum[d] = pre;  // sum over all 6 biases at column d
    }

    // Reduce the 6 partials across the block.
#pragma unroll
    for (int l = 0; l < L_DIM; ++l) {
#pragma unroll
        for (int o = 16; o > 0; o >>= 1)
            partialC[l] += __shfl_xor_sync(0xffffffffu, partialC[l], o);
    }
    __shared__ float sred[TPB / 32][L_DIM];
    const int warp = t >> 5, lane = t & 31;
    if (lane == 0) {
#pragma unroll
        for (int l = 0; l < L_DIM; ++l) sred[warp][l] = partialC[l];
    }
    __syncthreads();
    if (warp == 0) {
#pragma unroll
        for (int l = 0; l < L_DIM; ++l) {
            float v = (lane < TPB / 32) ? sred[lane][l] : 0.f;
#pragma unroll
            for (int o = 4; o > 0; o >>= 1)
                v += __shfl_xor_sync(0xffffffffu, v, o);
            if (lane == 0) g_C[l] = v;
        }
    }
}

// ---------------------------------------------------------------------------
// Kernel 2: one block per row. One pass: 6 dots -> scalar recurrence -> write.
// ---------------------------------------------------------------------------
__global__ __launch_bounds__(TPB) void cross_kernel(
    const float* __restrict__ x, const float* __restrict__ W,
    float* __restrict__ out)
{
    const int r = blockIdx.x;
    const int t = threadIdx.x;

    const float4* x4 = reinterpret_cast<const float4*>(x) + (size_t)r * D_VEC;
    const float4 xa = x4[t];
    const float4 xb = x4[t + TPB];

    // 6 dot-product partials against W rows (W is L2/L1 resident, 48 KB).
    float p[L_DIM];
#pragma unroll
    for (int l = 0; l < L_DIM; ++l) {
        const float4* w4 = reinterpret_cast<const float4*>(W) + l * D_VEC;
        const float4 wa = __ldg(&w4[t]);
        const float4 wb = __ldg(&w4[t + TPB]);
        p[l] = xa.x * wa.x + xa.y * wa.y + xa.z * wa.z + xa.w * wa.w
             + xb.x * wb.x + xb.y * wb.y + xb.z * wb.z + xb.w * wb.w;
    }

    // Warp-level reduction of all 6 partials (independent shuffle chains).
#pragma unroll
    for (int l = 0; l < L_DIM; ++l) {
#pragma unroll
        for (int o = 16; o > 0; o >>= 1)
            p[l] += __shfl_xor_sync(0xffffffffu, p[l], o);
    }

    // Cross-warp reduction: 8 warps -> 6 sums in shared memory.
    __shared__ float sred[TPB / 32][L_DIM];
    __shared__ float sd[L_DIM];
    const int warp = t >> 5, lane = t & 31;
    if (lane == 0) {
#pragma unroll
        for (int l = 0; l < L_DIM; ++l) sred[warp][l] = p[l];
    }
    __syncthreads();
    if (warp == 0) {
#pragma unroll
        for (int l = 0; l < L_DIM; ++l) {
            float v = (lane < TPB / 32) ? sred[lane][l] : 0.f;
#pragma unroll
            for (int o = 4; o > 0; o >>= 1)
                v += __shfl_xor_sync(0xffffffffu, v, o);
            if (lane == 0) sd[l] = v;
        }
    }
    __syncthreads();

    // Scalar recurrence (redundant across threads, trivially cheap).
    float alpha = 1.f;
#pragma unroll
    for (int l = 0; l < L_DIM; ++l) {
        const float s = alpha * sd[l] + g_C[l];
        alpha += s;
    }

    // out = alpha * x0 + bsum   (bsum is 8 KB, L1-resident)
    const float4* bs4 = reinterpret_cast<const float4*>(g_bsum);
    const float4 ba = bs4[t];
    const float4 bb = bs4[t + TPB];
    float4 oa, ob;
    oa.x = alpha * xa.x + ba.x;  oa.y = alpha * xa.y + ba.y;
    oa.z = alpha * xa.z + ba.z;  oa.w = alpha * xa.w + ba.w;
    ob.x = alpha * xb.x + bb.x;  ob.y = alpha * xb.y + bb.y;
    ob.z = alpha * xb.z + bb.z;  ob.w = alpha * xb.w + bb.w;

    float4* o4 = reinterpret_cast<float4*>(out) + (size_t)r * D_VEC;
    o4[t] = oa;
    o4[t + TPB] = ob;
}

// ---------------------------------------------------------------------------
extern "C" void kernel_launch(void* const* d_in, const int* in_sizes, int n_in,
                              void* d_out, int out_size)
{
    const float* x = (const float*)d_in[0];   // [B, 2048]
    const float* W = (const float*)d_in[1];   // [6, 2048]
    const float* b = (const float*)d_in[2];   // [6, 2048]
    float* out = (float*)d_out;               // [B, 2048]

    const int B = in_sizes[0] / D_DIM;

    precompute_kernel<<<1, TPB>>>(W, b);
    cross_kernel<<<B, TPB>>>(x, W, out);
}